// round 2
// baseline (speedup 1.0000x reference)
#include <cuda_runtime.h>
#include <cuda_bf16.h>
#include <cstdint>

// Problem constants (fixed by the dataset)
#define NN 100000      // nodes
#define NE 3200000     // edges
#define KD 512         // in dim
#define OD 64          // out dim

// Scratch (static device arrays: no allocation allowed)
__device__ float g_y[(size_t)NN * OD];   // y = dinv[n] * (X W)[n]
__device__ float g_deg[NN];              // in-degree at targets (float counts)

// ---------------------------------------------------------------------------
// 1) init: zero accumulator (d_out) and degree array
// ---------------------------------------------------------------------------
__global__ void init_kernel(float4* __restrict__ out4) {
    int i = blockIdx.x * blockDim.x + threadIdx.x;
    if (i < (NN * OD) / 4) out4[i] = make_float4(0.f, 0.f, 0.f, 0.f);
    if (i < NN) g_deg[i] = 0.f;
}

// ---------------------------------------------------------------------------
// 2) degree: deg[col[e]] += 1  (RED, result unused)
// ---------------------------------------------------------------------------
__global__ void degree_kernel(const int* __restrict__ col) {
    int e = blockIdx.x * blockDim.x + threadIdx.x;
    if (e < NE) {
        int d = col[e];
        atomicAdd(&g_deg[d], 1.0f);
    }
}

// ---------------------------------------------------------------------------
// 3) sgemm: y[n] = dinv[n] * (X[n,:] @ W)    BM=64, BN=64(all), BK=32,
//    256 threads, 4x4 per-thread tile, fp32 FFMA.
// ---------------------------------------------------------------------------
__global__ __launch_bounds__(256) void gemm_kernel(const float* __restrict__ X,
                                                   const float* __restrict__ W) {
    __shared__ float As[64][33];   // +1 pad: kills bank conflicts on column reads
    __shared__ float Ws[32][64];

    const int tid = threadIdx.x;
    const int tx = tid & 15;       // 0..15 -> 4 output cols each
    const int ty = tid >> 4;       // 0..15 -> 4 output rows each
    const int rowBase = blockIdx.x * 64;

    float acc[4][4] = {};

    // loader coordinates
    const int aRow = tid >> 3;         // 0..31
    const int aCol4 = (tid & 7) * 4;   // 0..28 step 4
    const int wRow = tid >> 4;         // 0..15
    const int wCol4 = (tid & 15) * 4;  // 0..60 step 4

    for (int k0 = 0; k0 < KD; k0 += 32) {
        #pragma unroll
        for (int rr = 0; rr < 2; rr++) {
            int r = aRow + rr * 32;
            int gr = rowBase + r;
            float4 v = make_float4(0.f, 0.f, 0.f, 0.f);
            if (gr < NN)
                v = *(const float4*)(X + (size_t)gr * KD + k0 + aCol4);
            As[r][aCol4 + 0] = v.x;
            As[r][aCol4 + 1] = v.y;
            As[r][aCol4 + 2] = v.z;
            As[r][aCol4 + 3] = v.w;
        }
        #pragma unroll
        for (int rr = 0; rr < 2; rr++) {
            int r = wRow + rr * 16;
            float4 v = *(const float4*)(W + (size_t)(k0 + r) * OD + wCol4);
            *(float4*)&Ws[r][wCol4] = v;
        }
        __syncthreads();

        #pragma unroll
        for (int kk = 0; kk < 32; kk++) {
            float a[4];
            #pragma unroll
            for (int i = 0; i < 4; i++) a[i] = As[ty * 4 + i][kk];
            float4 bv = *(float4*)&Ws[kk][tx * 4];
            float bb[4] = {bv.x, bv.y, bv.z, bv.w};
            #pragma unroll
            for (int i = 0; i < 4; i++)
                #pragma unroll
                for (int j = 0; j < 4; j++)
                    acc[i][j] += a[i] * bb[j];
        }
        __syncthreads();
    }

    // epilogue: scale row by dinv and write y
    #pragma unroll
    for (int i = 0; i < 4; i++) {
        int gr = rowBase + ty * 4 + i;
        if (gr < NN) {
            float dg = g_deg[gr];
            float d = dg > 0.f ? rsqrtf(dg) : 0.f;
            float4 v = make_float4(acc[i][0] * d, acc[i][1] * d,
                                   acc[i][2] * d, acc[i][3] * d);
            *(float4*)(g_y + (size_t)gr * OD + tx * 4) = v;
        }
    }
}

// ---------------------------------------------------------------------------
// 4) scatter: out[dst,:] += y[src,:]   16 threads per edge, float4 granules,
//    vector reductions (red.global.add.v4.f32)
// ---------------------------------------------------------------------------
__global__ __launch_bounds__(256) void scatter_kernel(const int* __restrict__ row,
                                                      const int* __restrict__ col,
                                                      float* __restrict__ out) {
    int t = blockIdx.x * 256 + threadIdx.x;
    int e = t >> 4;
    if (e >= NE) return;
    int c = (t & 15) * 4;
    int s = row[e];
    int d = col[e];
    float4 v = *(const float4*)(g_y + (size_t)s * OD + c);
    float* p = out + (size_t)d * OD + c;
    asm volatile("red.global.add.v4.f32 [%0], {%1,%2,%3,%4};"
                 :: "l"(p), "f"(v.x), "f"(v.y), "f"(v.z), "f"(v.w)
                 : "memory");
}

// ---------------------------------------------------------------------------
// 5) epilogue: out = PReLU(dinv[dst] * acc + b)
// ---------------------------------------------------------------------------
__global__ void epilogue_kernel(float4* __restrict__ out4,
                                const float* __restrict__ bias,
                                const float* __restrict__ prelu_a) {
    int t = blockIdx.x * blockDim.x + threadIdx.x;
    if (t >= (NN * OD) / 4) return;
    int n = t >> 4;          // node
    int c4 = (t & 15) * 4;   // column start
    float dg = g_deg[n];
    float d = dg > 0.f ? rsqrtf(dg) : 0.f;
    float a = prelu_a[0];
    float4 v = out4[t];
    float4 bb = *(const float4*)(bias + c4);
    v.x = v.x * d + bb.x;  v.x = v.x >= 0.f ? v.x : a * v.x;
    v.y = v.y * d + bb.y;  v.y = v.y >= 0.f ? v.y : a * v.y;
    v.z = v.z * d + bb.z;  v.z = v.z >= 0.f ? v.z : a * v.z;
    v.w = v.w * d + bb.w;  v.w = v.w >= 0.f ? v.w : a * v.w;
    out4[t] = v;
}

// ---------------------------------------------------------------------------
extern "C" void kernel_launch(void* const* d_in, const int* in_sizes, int n_in,
                              void* d_out, int out_size) {
    const float* X    = (const float*)d_in[0];   // [NN, KD] fp32
    const int*   eidx = (const int*)d_in[1];     // [2, NE] int32 (JAX default: int64 downcast)
    const float* W    = (const float*)d_in[2];   // [KD, OD]
    const float* bias = (const float*)d_in[3];   // [OD]
    const float* pa   = (const float*)d_in[4];   // [1]
    float* out = (float*)d_out;                  // [NN, OD]

    const int* row = eidx;        // sources
    const int* col = eidx + NE;   // targets

    // 1) zero accumulator + degrees
    {
        int n = (NN * OD) / 4;  // 1.6M (also covers NN)
        init_kernel<<<(n + 255) / 256, 256>>>((float4*)out);
    }
    // 2) in-degrees
    degree_kernel<<<(NE + 255) / 256, 256>>>(col);
    // 3) y = dinv * X W
    gemm_kernel<<<(NN + 63) / 64, 256>>>(X, W);
    // 4) out[dst] += y[src]
    {
        long long threads = (long long)NE * 16;
        scatter_kernel<<<(int)((threads + 255) / 256), 256>>>(row, col, out);
    }
    // 5) out = prelu(dinv*out + b)
    {
        int n = (NN * OD) / 4;
        epilogue_kernel<<<(n + 255) / 256, 256>>>((float4*)out, bias, pa);
    }
}

// round 3
// speedup vs baseline: 1.2606x; 1.2606x over previous
#include <cuda_runtime.h>
#include <cuda_bf16.h>
#include <cstdint>

#define NN 100000      // nodes
#define NE 3200000     // edges
#define KD 512         // in dim
#define OD 64          // out dim
#define SCAN_B 1024
#define NBLK ((NN + SCAN_B - 1) / SCAN_B)   // 98

// Scratch (static device arrays: no allocation allowed)
__device__ float g_y[(size_t)NN * OD];   // y = dinv[n] * (X W)[n]
__device__ int   g_degi[NN];             // in-degree (int)
__device__ float g_dinv[NN];             // d^-1/2
__device__ int   g_rowptr[NN + 1];       // CSR row pointers (by dst)
__device__ int   g_cursor[NN];           // fill cursors
__device__ int   g_srcs[NE];             // CSR column (src) indices
__device__ int   g_blocksums[NBLK];

// ---------------------------------------------------------------------------
// 1) zero degree counters
// ---------------------------------------------------------------------------
__global__ void init_deg_kernel() {
    int i = blockIdx.x * blockDim.x + threadIdx.x;
    if (i < NN) g_degi[i] = 0;
}

// ---------------------------------------------------------------------------
// 2) histogram of dst (4 edges / thread)
// ---------------------------------------------------------------------------
__global__ void hist_kernel(const int4* __restrict__ col4) {
    int i = blockIdx.x * blockDim.x + threadIdx.x;
    if (i < NE / 4) {
        int4 c = col4[i];
        atomicAdd(&g_degi[c.x], 1);
        atomicAdd(&g_degi[c.y], 1);
        atomicAdd(&g_degi[c.z], 1);
        atomicAdd(&g_degi[c.w], 1);
    }
}

// ---------------------------------------------------------------------------
// 3) scan phase A: per-block exclusive scan of degrees
// ---------------------------------------------------------------------------
__global__ __launch_bounds__(SCAN_B) void scanA_kernel() {
    __shared__ int s[SCAN_B];
    int t = threadIdx.x;
    int i = blockIdx.x * SCAN_B + t;
    int v = (i < NN) ? g_degi[i] : 0;
    s[t] = v;
    __syncthreads();
    for (int off = 1; off < SCAN_B; off <<= 1) {
        int x = (t >= off) ? s[t - off] : 0;
        __syncthreads();
        s[t] += x;
        __syncthreads();
    }
    if (i < NN) g_rowptr[i] = s[t] - v;         // exclusive, block-local
    if (t == SCAN_B - 1) g_blocksums[blockIdx.x] = s[t];
}

// 3b) scan phase B: scan the 98 block sums (one block)
__global__ void scanB_kernel() {
    __shared__ int s[128];
    int t = threadIdx.x;
    int v = (t < NBLK) ? g_blocksums[t] : 0;
    s[t] = v;
    __syncthreads();
    for (int off = 1; off < 128; off <<= 1) {
        int x = (t >= off) ? s[t - off] : 0;
        __syncthreads();
        s[t] += x;
        __syncthreads();
    }
    if (t < NBLK) g_blocksums[t] = s[t] - v;    // exclusive
}

// 3c) scan phase C: add offsets, init cursors, compute dinv
__global__ void scanC_kernel() {
    int i = blockIdx.x * blockDim.x + threadIdx.x;
    if (i < NN) {
        int r = g_rowptr[i] + g_blocksums[i >> 10];
        g_rowptr[i] = r;
        g_cursor[i] = r;
        int dg = g_degi[i];
        g_dinv[i] = dg > 0 ? rsqrtf((float)dg) : 0.f;
    } else if (i == NN) {
        g_rowptr[NN] = NE;
    }
}

// ---------------------------------------------------------------------------
// 4) fill CSR: srcs[pos] = row[e], ordered by dst
// ---------------------------------------------------------------------------
__global__ void fill_kernel(const int4* __restrict__ row4,
                            const int4* __restrict__ col4) {
    int i = blockIdx.x * blockDim.x + threadIdx.x;
    if (i < NE / 4) {
        int4 c = col4[i];
        int4 r = row4[i];
        int p0 = atomicAdd(&g_cursor[c.x], 1); g_srcs[p0] = r.x;
        int p1 = atomicAdd(&g_cursor[c.y], 1); g_srcs[p1] = r.y;
        int p2 = atomicAdd(&g_cursor[c.z], 1); g_srcs[p2] = r.z;
        int p3 = atomicAdd(&g_cursor[c.w], 1); g_srcs[p3] = r.w;
    }
}

// ---------------------------------------------------------------------------
// 5) sgemm: y[n] = dinv[n] * (X[n,:] @ W)
//    BM=128, BN=64, BK=32, 256 threads, 8x4 per thread,
//    k-major SMEM A (LDS.128 reads), double-buffered, reg prefetch.
// ---------------------------------------------------------------------------
__global__ __launch_bounds__(256) void gemm_kernel(const float* __restrict__ X,
                                                   const float* __restrict__ W) {
    __shared__ float Ast[2][32][128];  // [buf][k][row]  k-major
    __shared__ float Ws[2][32][64];    // [buf][k][col]

    const int tid = threadIdx.x;
    const int tx = tid & 15;       // 4 output cols each
    const int ty = tid >> 4;       // 8 output rows each
    const int rowBase = blockIdx.x * 128;

    // A loader: row r = tid>>1, 16 k-values starting at (tid&1)*16
    const int aRow = tid >> 1;
    const int aK0  = (tid & 1) * 16;
    // W loader: 2 float4 per thread
    const int wRow = tid >> 3;            // 0..31
    const int wC0  = (tid & 7) * 8;       // 0..56 step 8

    float acc[8][4] = {};
    float4 ra[4];      // A prefetch regs (16 floats)
    float4 rw[2];      // W prefetch regs

    const int grA = rowBase + aRow;
    const bool okA = grA < NN;
    const float* Xrow = X + (size_t)grA * KD;

    // prefetch tile 0
    {
        #pragma unroll
        for (int j = 0; j < 4; j++)
            ra[j] = okA ? *(const float4*)(Xrow + aK0 + j * 4)
                        : make_float4(0.f, 0.f, 0.f, 0.f);
        rw[0] = *(const float4*)(W + (size_t)wRow * OD + wC0);
        rw[1] = *(const float4*)(W + (size_t)wRow * OD + wC0 + 4);
    }
    // store tile 0
    #pragma unroll
    for (int j = 0; j < 4; j++) {
        Ast[0][aK0 + j * 4 + 0][aRow] = ra[j].x;
        Ast[0][aK0 + j * 4 + 1][aRow] = ra[j].y;
        Ast[0][aK0 + j * 4 + 2][aRow] = ra[j].z;
        Ast[0][aK0 + j * 4 + 3][aRow] = ra[j].w;
    }
    *(float4*)&Ws[0][wRow][wC0]     = rw[0];
    *(float4*)&Ws[0][wRow][wC0 + 4] = rw[1];
    __syncthreads();

    const int NT = KD / 32;   // 16 k-tiles
    for (int kt = 0; kt < NT; kt++) {
        const int b = kt & 1;
        // prefetch next tile into regs
        if (kt + 1 < NT) {
            int k0 = (kt + 1) * 32;
            #pragma unroll
            for (int j = 0; j < 4; j++)
                ra[j] = okA ? *(const float4*)(Xrow + k0 + aK0 + j * 4)
                            : make_float4(0.f, 0.f, 0.f, 0.f);
            rw[0] = *(const float4*)(W + (size_t)(k0 + wRow) * OD + wC0);
            rw[1] = *(const float4*)(W + (size_t)(k0 + wRow) * OD + wC0 + 4);
        }
        // compute current tile
        #pragma unroll
        for (int kk = 0; kk < 32; kk++) {
            float4 a0 = *(float4*)&Ast[b][kk][ty * 8];
            float4 a1 = *(float4*)&Ast[b][kk][ty * 8 + 4];
            float4 bv = *(float4*)&Ws[b][kk][tx * 4];
            float av[8] = {a0.x, a0.y, a0.z, a0.w, a1.x, a1.y, a1.z, a1.w};
            float bb[4] = {bv.x, bv.y, bv.z, bv.w};
            #pragma unroll
            for (int i = 0; i < 8; i++)
                #pragma unroll
                for (int j = 0; j < 4; j++)
                    acc[i][j] += av[i] * bb[j];
        }
        // store next tile
        if (kt + 1 < NT) {
            const int nb = (kt + 1) & 1;
            #pragma unroll
            for (int j = 0; j < 4; j++) {
                Ast[nb][aK0 + j * 4 + 0][aRow] = ra[j].x;
                Ast[nb][aK0 + j * 4 + 1][aRow] = ra[j].y;
                Ast[nb][aK0 + j * 4 + 2][aRow] = ra[j].z;
                Ast[nb][aK0 + j * 4 + 3][aRow] = ra[j].w;
            }
            *(float4*)&Ws[nb][wRow][wC0]     = rw[0];
            *(float4*)&Ws[nb][wRow][wC0 + 4] = rw[1];
            __syncthreads();
        }
    }

    // epilogue: scale by dinv[row], write y
    #pragma unroll
    for (int i = 0; i < 8; i++) {
        int gr = rowBase + ty * 8 + i;
        if (gr < NN) {
            float d = g_dinv[gr];
            float4 v = make_float4(acc[i][0] * d, acc[i][1] * d,
                                   acc[i][2] * d, acc[i][3] * d);
            *(float4*)(g_y + (size_t)gr * OD + tx * 4) = v;
        }
    }
}

// ---------------------------------------------------------------------------
// 6) gather: out[n] = prelu(dinv[n] * sum_{e in CSR(n)} y[src(e)] + b)
//    16 threads per node, float4 per thread, register accumulation.
// ---------------------------------------------------------------------------
__global__ __launch_bounds__(256) void gather_kernel(float* __restrict__ out,
                                                     const float* __restrict__ bias,
                                                     const float* __restrict__ prelu_a) {
    int t = blockIdx.x * 256 + threadIdx.x;
    int n = t >> 4;
    if (n >= NN) return;
    int c = t & 15;                       // float4 column index
    const float4* y4 = (const float4*)g_y;

    int beg = g_rowptr[n];
    int end = g_rowptr[n + 1];

    float4 acc = make_float4(0.f, 0.f, 0.f, 0.f);
    int i = beg;
    for (; i + 4 <= end; i += 4) {
        int s0 = g_srcs[i], s1 = g_srcs[i + 1], s2 = g_srcs[i + 2], s3 = g_srcs[i + 3];
        float4 v0 = y4[(size_t)s0 * 16 + c];
        float4 v1 = y4[(size_t)s1 * 16 + c];
        float4 v2 = y4[(size_t)s2 * 16 + c];
        float4 v3 = y4[(size_t)s3 * 16 + c];
        acc.x += v0.x + v1.x + v2.x + v3.x;
        acc.y += v0.y + v1.y + v2.y + v3.y;
        acc.z += v0.z + v1.z + v2.z + v3.z;
        acc.w += v0.w + v1.w + v2.w + v3.w;
    }
    for (; i < end; i++) {
        int s = g_srcs[i];
        float4 v = y4[(size_t)s * 16 + c];
        acc.x += v.x; acc.y += v.y; acc.z += v.z; acc.w += v.w;
    }

    float d = g_dinv[n];
    float a = prelu_a[0];
    float4 bb = ((const float4*)bias)[c];
    float4 r;
    r.x = acc.x * d + bb.x;  r.x = r.x >= 0.f ? r.x : a * r.x;
    r.y = acc.y * d + bb.y;  r.y = r.y >= 0.f ? r.y : a * r.y;
    r.z = acc.z * d + bb.z;  r.z = r.z >= 0.f ? r.z : a * r.z;
    r.w = acc.w * d + bb.w;  r.w = r.w >= 0.f ? r.w : a * r.w;
    ((float4*)out)[(size_t)n * 16 + c] = r;
}

// ---------------------------------------------------------------------------
extern "C" void kernel_launch(void* const* d_in, const int* in_sizes, int n_in,
                              void* d_out, int out_size) {
    const float* X    = (const float*)d_in[0];   // [NN, KD]
    const int*   eidx = (const int*)d_in[1];     // [2, NE] int32
    const float* W    = (const float*)d_in[2];   // [KD, OD]
    const float* bias = (const float*)d_in[3];   // [OD]
    const float* pa   = (const float*)d_in[4];   // [1]
    float* out = (float*)d_out;                  // [NN, OD]

    const int* row = eidx;        // sources
    const int* col = eidx + NE;   // targets

    init_deg_kernel<<<(NN + 255) / 256, 256>>>();
    hist_kernel<<<(NE / 4 + 255) / 256, 256>>>((const int4*)col);
    scanA_kernel<<<NBLK, SCAN_B>>>();
    scanB_kernel<<<1, 128>>>();
    scanC_kernel<<<(NN + 1 + 255) / 256, 256>>>();
    fill_kernel<<<(NE / 4 + 255) / 256, 256>>>((const int4*)row, (const int4*)col);
    gemm_kernel<<<(NN + 127) / 128, 256>>>(X, W);
    gather_kernel<<<(NN * 16 + 255) / 256, 256>>>(out, bias, pa);
}